// round 1
// baseline (speedup 1.0000x reference)
#include <cuda_runtime.h>
#include <math.h>

#define T_SEQ 2048
#define D_DIM 768
#define B_BATCH 8
#define OUT_D 1536
#define SCALE 0.03608439182435161f  // 1/sqrt(768)

// Scratch: S/P matrix [B, T, T] fp32 = 134 MB. Static __device__ array (no allocs allowed).
__device__ float g_S[(size_t)B_BATCH * T_SEQ * T_SEQ];

// ---------------------------------------------------------------------------
// Kernel 1: S[b,i,j] = scale * dot(X[b,i,:], X[b,j,:])  for lower-tri blocks.
// 128x128x16 tile, 256 threads, 8x8 microtile (split 4+4 for conflict-free LDS).
// ---------------------------------------------------------------------------
__global__ __launch_bounds__(256) void qk_kernel(const float* __restrict__ X) {
    const int bj = blockIdx.x;   // key tile
    const int bi = blockIdx.y;   // query tile
    const int b  = blockIdx.z;
    if (bj > bi) return;         // strictly-above-diagonal blocks: all masked

    const float* A  = X + ((size_t)b * T_SEQ + (size_t)bi * 128) * D_DIM;
    const float* Bp = X + ((size_t)b * T_SEQ + (size_t)bj * 128) * D_DIM;
    float* C = g_S + ((size_t)b * T_SEQ + (size_t)bi * 128) * T_SEQ + (size_t)bj * 128;

    __shared__ float As[16][128];
    __shared__ float Bs[16][128];

    const int tid = threadIdx.x;
    const int tx = tid & 15;
    const int ty = tid >> 4;
    const int lrow = tid >> 2;          // 0..63
    const int lcol = (tid & 3) << 2;    // 0,4,8,12

    float acc[8][8];
#pragma unroll
    for (int i = 0; i < 8; ++i)
#pragma unroll
        for (int j = 0; j < 8; ++j) acc[i][j] = 0.0f;

    for (int k0 = 0; k0 < D_DIM; k0 += 16) {
#pragma unroll
        for (int r = 0; r < 2; ++r) {
            const int row = lrow + 64 * r;
            const float4 va = *reinterpret_cast<const float4*>(A + (size_t)row * D_DIM + k0 + lcol);
            As[lcol + 0][row] = va.x; As[lcol + 1][row] = va.y;
            As[lcol + 2][row] = va.z; As[lcol + 3][row] = va.w;
            const float4 vb = *reinterpret_cast<const float4*>(Bp + (size_t)row * D_DIM + k0 + lcol);
            Bs[lcol + 0][row] = vb.x; Bs[lcol + 1][row] = vb.y;
            Bs[lcol + 2][row] = vb.z; Bs[lcol + 3][row] = vb.w;
        }
        __syncthreads();
#pragma unroll
        for (int k = 0; k < 16; ++k) {
            const float4 a0 = *reinterpret_cast<const float4*>(&As[k][ty * 4]);
            const float4 a1 = *reinterpret_cast<const float4*>(&As[k][64 + ty * 4]);
            const float4 b0 = *reinterpret_cast<const float4*>(&Bs[k][tx * 4]);
            const float4 b1 = *reinterpret_cast<const float4*>(&Bs[k][64 + tx * 4]);
            const float ar[8] = {a0.x, a0.y, a0.z, a0.w, a1.x, a1.y, a1.z, a1.w};
            const float br[8] = {b0.x, b0.y, b0.z, b0.w, b1.x, b1.y, b1.z, b1.w};
#pragma unroll
            for (int mi = 0; mi < 8; ++mi)
#pragma unroll
                for (int ni = 0; ni < 8; ++ni)
                    acc[mi][ni] += ar[mi] * br[ni];
        }
        __syncthreads();
    }

#pragma unroll
    for (int mi = 0; mi < 8; ++mi) {
        const int m = (mi < 4) ? (ty * 4 + mi) : (64 + ty * 4 + mi - 4);
        float4 v0, v1;
        v0.x = acc[mi][0] * SCALE; v0.y = acc[mi][1] * SCALE;
        v0.z = acc[mi][2] * SCALE; v0.w = acc[mi][3] * SCALE;
        v1.x = acc[mi][4] * SCALE; v1.y = acc[mi][5] * SCALE;
        v1.z = acc[mi][6] * SCALE; v1.w = acc[mi][7] * SCALE;
        *reinterpret_cast<float4*>(&C[(size_t)m * T_SEQ + tx * 4]) = v0;
        *reinterpret_cast<float4*>(&C[(size_t)m * T_SEQ + 64 + tx * 4]) = v1;
    }
}

// ---------------------------------------------------------------------------
// Kernel 2: per-row softmax over j<=i (denominator unmasked), then zero by
// sit_mask (post-softmax, no renorm). Writes zeros for j>i so PV can read
// full blocks. Also fuses the concat copy out[b,i,768:1536] = X[b,i,:].
// ---------------------------------------------------------------------------
__global__ __launch_bounds__(256) void softmax_concat_kernel(
    const float* __restrict__ X, const float* __restrict__ sm,
    float* __restrict__ out) {
    const int i = blockIdx.x;
    const int b = blockIdx.y;
    float* row = g_S + ((size_t)b * T_SEQ + i) * T_SEQ;
    const int len = i + 1;
    const int tid = threadIdx.x;

    __shared__ float red[8];
    __shared__ float bcast;

    // --- max over j <= i ---
    float v = -INFINITY;
    for (int j = tid; j < len; j += 256) v = fmaxf(v, row[j]);
#pragma unroll
    for (int o = 16; o; o >>= 1) v = fmaxf(v, __shfl_xor_sync(0xffffffffu, v, o));
    if ((tid & 31) == 0) red[tid >> 5] = v;
    __syncthreads();
    if (tid == 0) {
        float t = red[0];
#pragma unroll
        for (int w = 1; w < 8; ++w) t = fmaxf(t, red[w]);
        bcast = t;
    }
    __syncthreads();
    const float m = bcast;
    __syncthreads();

    // --- sum of exp over j <= i ---
    float s = 0.0f;
    for (int j = tid; j < len; j += 256) s += __expf(row[j] - m);
#pragma unroll
    for (int o = 16; o; o >>= 1) s += __shfl_xor_sync(0xffffffffu, s, o);
    if ((tid & 31) == 0) red[tid >> 5] = s;
    __syncthreads();
    if (tid == 0) {
        float t = 0.0f;
#pragma unroll
        for (int w = 0; w < 8; ++w) t += red[w];
        bcast = t;
    }
    __syncthreads();
    const float L = bcast;

    const float mi = sm[(size_t)b * T_SEQ + i];
    const float inv = (mi != 0.0f) ? (1.0f / L) : 0.0f;   // query masked -> whole row zero

    for (int j = tid; j < T_SEQ; j += 256) {
        float p = 0.0f;
        if (j < len) {
            const float mj = sm[(size_t)b * T_SEQ + j];
            p = (mj != 0.0f) ? __expf(row[j] - m) * inv : 0.0f;
        }
        row[j] = p;
    }

    // concat: second half of output
    const float* xr = X + ((size_t)b * T_SEQ + i) * D_DIM;
    float* orow = out + ((size_t)b * T_SEQ + i) * OUT_D + D_DIM;
    for (int d = tid; d < D_DIM; d += 256) orow[d] = xr[d];
}

// ---------------------------------------------------------------------------
// Kernel 3: out[b,i,0:768] = P[b,i,:] @ X[b,:,:]. GEMM-NN 128x128x16,
// k-loop truncated at (bi+1)*128 (causal). Output row stride 1536 (concat).
// ---------------------------------------------------------------------------
__global__ __launch_bounds__(256) void pv_kernel(const float* __restrict__ X,
                                                 float* __restrict__ out) {
    const int bn = blockIdx.x;   // output d tile (0..5)
    const int bi = blockIdx.y;   // query tile
    const int b  = blockIdx.z;

    const float* A  = g_S + ((size_t)b * T_SEQ + (size_t)bi * 128) * T_SEQ;
    const float* Bp = X + (size_t)b * T_SEQ * D_DIM + (size_t)bn * 128;
    float* C = out + ((size_t)b * T_SEQ + (size_t)bi * 128) * OUT_D + (size_t)bn * 128;
    const int kmax = (bi + 1) * 128;

    __shared__ float As[16][128];
    __shared__ float Bs[16][128];

    const int tid = threadIdx.x;
    const int tx = tid & 15;
    const int ty = tid >> 4;
    const int lrow = tid >> 2;          // A loader: 0..63
    const int lcol = (tid & 3) << 2;
    const int brow = tid >> 5;          // B loader: 0..7
    const int bcol = (tid & 31) << 2;   // 0..124

    float acc[8][8];
#pragma unroll
    for (int i = 0; i < 8; ++i)
#pragma unroll
        for (int j = 0; j < 8; ++j) acc[i][j] = 0.0f;

    for (int k0 = 0; k0 < kmax; k0 += 16) {
#pragma unroll
        for (int r = 0; r < 2; ++r) {
            const int row = lrow + 64 * r;
            const float4 va = *reinterpret_cast<const float4*>(A + (size_t)row * T_SEQ + k0 + lcol);
            As[lcol + 0][row] = va.x; As[lcol + 1][row] = va.y;
            As[lcol + 2][row] = va.z; As[lcol + 3][row] = va.w;
            const int jr = brow + 8 * r;
            const float4 vb = *reinterpret_cast<const float4*>(Bp + (size_t)(k0 + jr) * D_DIM + bcol);
            *reinterpret_cast<float4*>(&Bs[jr][bcol]) = vb;
        }
        __syncthreads();
#pragma unroll
        for (int k = 0; k < 16; ++k) {
            const float4 a0 = *reinterpret_cast<const float4*>(&As[k][ty * 4]);
            const float4 a1 = *reinterpret_cast<const float4*>(&As[k][64 + ty * 4]);
            const float4 b0 = *reinterpret_cast<const float4*>(&Bs[k][tx * 4]);
            const float4 b1 = *reinterpret_cast<const float4*>(&Bs[k][64 + tx * 4]);
            const float ar[8] = {a0.x, a0.y, a0.z, a0.w, a1.x, a1.y, a1.z, a1.w};
            const float br[8] = {b0.x, b0.y, b0.z, b0.w, b1.x, b1.y, b1.z, b1.w};
#pragma unroll
            for (int mi = 0; mi < 8; ++mi)
#pragma unroll
                for (int ni = 0; ni < 8; ++ni)
                    acc[mi][ni] += ar[mi] * br[ni];
        }
        __syncthreads();
    }

#pragma unroll
    for (int mi = 0; mi < 8; ++mi) {
        const int m = (mi < 4) ? (ty * 4 + mi) : (64 + ty * 4 + mi - 4);
        float4 v0, v1;
        v0.x = acc[mi][0]; v0.y = acc[mi][1]; v0.z = acc[mi][2]; v0.w = acc[mi][3];
        v1.x = acc[mi][4]; v1.y = acc[mi][5]; v1.z = acc[mi][6]; v1.w = acc[mi][7];
        *reinterpret_cast<float4*>(&C[(size_t)m * OUT_D + tx * 4]) = v0;
        *reinterpret_cast<float4*>(&C[(size_t)m * OUT_D + 64 + tx * 4]) = v1;
    }
}

// ---------------------------------------------------------------------------
// Inputs (metadata order): [0] text_inputs [8,2048,768] f32,
// [1] sit_mask [8,2048] f32, [2] proposition_matrix (unused).
// Output: [8,2048,1536] f32.
// ---------------------------------------------------------------------------
extern "C" void kernel_launch(void* const* d_in, const int* in_sizes, int n_in,
                              void* d_out, int out_size) {
    const float* X  = (const float*)d_in[0];
    const float* sm = (const float*)d_in[1];
    float* out = (float*)d_out;

    qk_kernel<<<dim3(16, 16, B_BATCH), 256>>>(X);
    softmax_concat_kernel<<<dim3(T_SEQ, B_BATCH), 256>>>(X, sm, out);
    pv_kernel<<<dim3(6, 16, B_BATCH), 256>>>(X, out);
}

// round 3
// speedup vs baseline: 2.1338x; 2.1338x over previous
#include <cuda_runtime.h>
#include <math.h>

#define T_SEQ 2048
#define D_DIM 768
#define B_BATCH 8
#define OUT_D 1536
#define SCALE 0.03608439182435161f  // 1/sqrt(768)

// Scratch: S/P matrix [B, T, T] fp32 = 134 MB.
__device__ float g_S[(size_t)B_BATCH * T_SEQ * T_SEQ];

__device__ __forceinline__ unsigned f2tf32(float f) {
    unsigned u;
    asm("cvt.rna.tf32.f32 %0, %1;" : "=r"(u) : "f"(f));
    return u;
}

__device__ __forceinline__ void mma_tf32(float c[4], unsigned a0, unsigned a1,
                                         unsigned a2, unsigned a3,
                                         unsigned b0, unsigned b1) {
    asm volatile(
        "mma.sync.aligned.m16n8k8.row.col.f32.tf32.tf32.f32 "
        "{%0,%1,%2,%3}, {%4,%5,%6,%7}, {%8,%9}, {%0,%1,%2,%3};"
        : "+f"(c[0]), "+f"(c[1]), "+f"(c[2]), "+f"(c[3])
        : "r"(a0), "r"(a1), "r"(a2), "r"(a3), "r"(b0), "r"(b1));
}

// Shared-tile stride: (tg*136 + g) mod 32 covers banks 0..31 -> conflict-free frag loads.
#define LDS_STRIDE 136

// ---------------------------------------------------------------------------
// Kernel 1: S = scale * X X^T for lower-tri blocks. TF32 mma, 128x128 tile.
// ---------------------------------------------------------------------------
__global__ __launch_bounds__(256) void qk_kernel(const float* __restrict__ X) {
    const int bj = blockIdx.x;
    const int bi = blockIdx.y;
    const int b  = blockIdx.z;
    if (bj > bi) return;

    const float* Ag = X + ((size_t)b * T_SEQ + (size_t)bi * 128) * D_DIM;
    const float* Bg = X + ((size_t)b * T_SEQ + (size_t)bj * 128) * D_DIM;
    float* C = g_S + ((size_t)b * T_SEQ + (size_t)bi * 128) * T_SEQ + (size_t)bj * 128;

    __shared__ unsigned As[16][LDS_STRIDE];
    __shared__ unsigned Bs[16][LDS_STRIDE];

    const int tid  = threadIdx.x;
    const int lane = tid & 31;
    const int warp = tid >> 5;
    const int g    = lane >> 2;      // group id 0..7
    const int tg   = lane & 3;       // thread-in-group 0..3
    const int wm   = (warp & 1) * 64;
    const int wn   = (warp >> 1) * 32;

    const int lm   = tid >> 1;       // loader row 0..127
    const int lh   = tid & 1;        // loader half

    float c[4][4][4];
#pragma unroll
    for (int i = 0; i < 4; ++i)
#pragma unroll
        for (int j = 0; j < 4; ++j)
#pragma unroll
            for (int r = 0; r < 4; ++r) c[i][j][r] = 0.0f;

    for (int k0 = 0; k0 < D_DIM; k0 += 16) {
        // transpose loaders: As[k][m] = Ag[m][k0+k] (tf32), same for Bs
#pragma unroll
        for (int r = 0; r < 2; ++r) {
            const int cc = lh * 2 + r;           // float4 index along k
            float4 va = *reinterpret_cast<const float4*>(Ag + (size_t)lm * D_DIM + k0 + 4 * cc);
            As[4 * cc + 0][lm] = f2tf32(va.x); As[4 * cc + 1][lm] = f2tf32(va.y);
            As[4 * cc + 2][lm] = f2tf32(va.z); As[4 * cc + 3][lm] = f2tf32(va.w);
            float4 vb = *reinterpret_cast<const float4*>(Bg + (size_t)lm * D_DIM + k0 + 4 * cc);
            Bs[4 * cc + 0][lm] = f2tf32(vb.x); Bs[4 * cc + 1][lm] = f2tf32(vb.y);
            Bs[4 * cc + 2][lm] = f2tf32(vb.z); Bs[4 * cc + 3][lm] = f2tf32(vb.w);
        }
        __syncthreads();

#pragma unroll
        for (int ks = 0; ks < 16; ks += 8) {
            unsigned a[4][4], bf[4][2];
#pragma unroll
            for (int mt = 0; mt < 4; ++mt) {
                const int m = wm + mt * 16 + g;
                a[mt][0] = As[ks + tg][m];
                a[mt][1] = As[ks + tg][m + 8];
                a[mt][2] = As[ks + tg + 4][m];
                a[mt][3] = As[ks + tg + 4][m + 8];
            }
#pragma unroll
            for (int nt = 0; nt < 4; ++nt) {
                const int n = wn + nt * 8 + g;
                bf[nt][0] = Bs[ks + tg][n];
                bf[nt][1] = Bs[ks + tg + 4][n];
            }
#pragma unroll
            for (int mt = 0; mt < 4; ++mt)
#pragma unroll
                for (int nt = 0; nt < 4; ++nt)
                    mma_tf32(c[mt][nt], a[mt][0], a[mt][1], a[mt][2], a[mt][3],
                             bf[nt][0], bf[nt][1]);
        }
        __syncthreads();
    }

#pragma unroll
    for (int mt = 0; mt < 4; ++mt) {
#pragma unroll
        for (int nt = 0; nt < 4; ++nt) {
            const int m = wm + mt * 16 + g;
            const int n = wn + nt * 8 + 2 * tg;
            float2 v0 = make_float2(c[mt][nt][0] * SCALE, c[mt][nt][1] * SCALE);
            float2 v1 = make_float2(c[mt][nt][2] * SCALE, c[mt][nt][3] * SCALE);
            *reinterpret_cast<float2*>(&C[(size_t)m * T_SEQ + n]) = v0;
            *reinterpret_cast<float2*>(&C[(size_t)(m + 8) * T_SEQ + n]) = v1;
        }
    }
}

// ---------------------------------------------------------------------------
// Kernel 2: per-row softmax over j<=i (denominator unmasked), post-softmax
// sit_mask zeroing (no renorm). Row cached in smem (one global read).
// Zero-fill only [len, ceil(len,128)) -- the only region PV reads.
// Fuses concat copy out[b,i,768:] = X[b,i,:].
// ---------------------------------------------------------------------------
__global__ __launch_bounds__(256) void softmax_concat_kernel(
    const float* __restrict__ X, const float* __restrict__ sm,
    float* __restrict__ out) {
    const int i = blockIdx.x;
    const int b = blockIdx.y;
    float* row = g_S + ((size_t)b * T_SEQ + i) * T_SEQ;
    const int len = i + 1;
    const int len_pad = ((i >> 7) + 1) << 7;
    const int tid = threadIdx.x;

    __shared__ float srow[T_SEQ];
    __shared__ float red[8];
    __shared__ float bcast;

    float v = -INFINITY;
    for (int j = tid; j < len; j += 256) {
        const float x = row[j];
        srow[j] = x;
        v = fmaxf(v, x);
    }
#pragma unroll
    for (int o = 16; o; o >>= 1) v = fmaxf(v, __shfl_xor_sync(0xffffffffu, v, o));
    if ((tid & 31) == 0) red[tid >> 5] = v;
    __syncthreads();
    if (tid == 0) {
        float t = red[0];
#pragma unroll
        for (int w = 1; w < 8; ++w) t = fmaxf(t, red[w]);
        bcast = t;
    }
    __syncthreads();
    const float m = bcast;
    __syncthreads();

    float s = 0.0f;
    for (int j = tid; j < len; j += 256) s += __expf(srow[j] - m);
#pragma unroll
    for (int o = 16; o; o >>= 1) s += __shfl_xor_sync(0xffffffffu, s, o);
    if ((tid & 31) == 0) red[tid >> 5] = s;
    __syncthreads();
    if (tid == 0) {
        float t = 0.0f;
#pragma unroll
        for (int w = 0; w < 8; ++w) t += red[w];
        bcast = t;
    }
    __syncthreads();
    const float L = bcast;

    const float mi = sm[(size_t)b * T_SEQ + i];
    const float inv = (mi != 0.0f) ? (1.0f / L) : 0.0f;

    for (int j = tid; j < len; j += 256) {
        const float mj = sm[(size_t)b * T_SEQ + j];
        row[j] = (mj != 0.0f) ? __expf(srow[j] - m) * inv : 0.0f;
    }
    for (int j = len + tid; j < len_pad; j += 256) row[j] = 0.0f;

    // concat second half
    const float* xr = X + ((size_t)b * T_SEQ + i) * D_DIM;
    float* orow = out + ((size_t)b * T_SEQ + i) * OUT_D + D_DIM;
    for (int d = tid * 4; d < D_DIM; d += 1024)
        *reinterpret_cast<float4*>(&orow[d]) =
            *reinterpret_cast<const float4*>(&xr[d]);
}

// ---------------------------------------------------------------------------
// Kernel 3: out[:, :768] = P @ X. TF32 mma, 128x128 tile, causal k-truncation.
// ---------------------------------------------------------------------------
__global__ __launch_bounds__(256) void pv_kernel(const float* __restrict__ X,
                                                 float* __restrict__ out) {
    const int bn = blockIdx.x;   // d tile 0..5
    const int bi = blockIdx.y;
    const int b  = blockIdx.z;

    const float* Ag = g_S + ((size_t)b * T_SEQ + (size_t)bi * 128) * T_SEQ;
    const float* Bg = X + (size_t)b * T_SEQ * D_DIM + (size_t)bn * 128;
    float* C = out + ((size_t)b * T_SEQ + (size_t)bi * 128) * OUT_D + (size_t)bn * 128;
    const int kmax = (bi + 1) * 128;

    __shared__ unsigned As[16][LDS_STRIDE];
    __shared__ unsigned Bs[16][LDS_STRIDE];

    const int tid  = threadIdx.x;
    const int lane = tid & 31;
    const int warp = tid >> 5;
    const int g    = lane >> 2;
    const int tg   = lane & 3;
    const int wm   = (warp & 1) * 64;
    const int wn   = (warp >> 1) * 32;

    const int lm   = tid >> 1;
    const int lh   = tid & 1;
    const int bkr  = tid >> 4;       // B loader: k row 0..15
    const int bnc  = tid & 15;       // B loader: n chunk

    float c[4][4][4];
#pragma unroll
    for (int i = 0; i < 4; ++i)
#pragma unroll
        for (int j = 0; j < 4; ++j)
#pragma unroll
            for (int r = 0; r < 4; ++r) c[i][j][r] = 0.0f;

    for (int k0 = 0; k0 < kmax; k0 += 16) {
        // A (P) transpose loader
#pragma unroll
        for (int r = 0; r < 2; ++r) {
            const int cc = lh * 2 + r;
            float4 va = *reinterpret_cast<const float4*>(Ag + (size_t)lm * T_SEQ + k0 + 4 * cc);
            As[4 * cc + 0][lm] = f2tf32(va.x); As[4 * cc + 1][lm] = f2tf32(va.y);
            As[4 * cc + 2][lm] = f2tf32(va.z); As[4 * cc + 3][lm] = f2tf32(va.w);
        }
        // B (X) direct loader: Bs[k][n] = X[k0+k][dbase+n]
#pragma unroll
        for (int r = 0; r < 2; ++r) {
            const int n = bnc * 4 + r * 64;
            float4 vb = *reinterpret_cast<const float4*>(Bg + (size_t)(k0 + bkr) * D_DIM + n);
            uint4 t;
            t.x = f2tf32(vb.x); t.y = f2tf32(vb.y);
            t.z = f2tf32(vb.z); t.w = f2tf32(vb.w);
            *reinterpret_cast<uint4*>(&Bs[bkr][n]) = t;
        }
        __syncthreads();

#pragma unroll
        for (int ks = 0; ks < 16; ks += 8) {
            unsigned a[4][4], bf[4][2];
#pragma unroll
            for (int mt = 0; mt < 4; ++mt) {
                const int m = wm + mt * 16 + g;
                a[mt][0] = As[ks + tg][m];
                a[mt][1] = As[ks + tg][m + 8];
                a[mt][2] = As[ks + tg + 4][m];
                a[mt][3] = As[ks + tg + 4][m + 8];
            }
#pragma unroll
            for (int nt = 0; nt < 4; ++nt) {
                const int n = wn + nt * 8 + g;
                bf[nt][0] = Bs[ks + tg][n];
                bf[nt][1] = Bs[ks + tg + 4][n];
            }
#pragma unroll
            for (int mt = 0; mt < 4; ++mt)
#pragma unroll
                for (int nt = 0; nt < 4; ++nt)
                    mma_tf32(c[mt][nt], a[mt][0], a[mt][1], a[mt][2], a[mt][3],
                             bf[nt][0], bf[nt][1]);
        }
        __syncthreads();
    }

#pragma unroll
    for (int mt = 0; mt < 4; ++mt) {
#pragma unroll
        for (int nt = 0; nt < 4; ++nt) {
            const int m = wm + mt * 16 + g;
            const int n = wn + nt * 8 + 2 * tg;
            float2 v0 = make_float2(c[mt][nt][0], c[mt][nt][1]);
            float2 v1 = make_float2(c[mt][nt][2], c[mt][nt][3]);
            *reinterpret_cast<float2*>(&C[(size_t)m * OUT_D + n]) = v0;
            *reinterpret_cast<float2*>(&C[(size_t)(m + 8) * OUT_D + n]) = v1;
        }
    }
}

// ---------------------------------------------------------------------------
// Inputs: [0] text_inputs [8,2048,768] f32, [1] sit_mask [8,2048] f32,
// [2] proposition_matrix (unused). Output: [8,2048,1536] f32.
// ---------------------------------------------------------------------------
extern "C" void kernel_launch(void* const* d_in, const int* in_sizes, int n_in,
                              void* d_out, int out_size) {
    const float* X  = (const float*)d_in[0];
    const float* sm = (const float*)d_in[1];
    float* out = (float*)d_out;

    qk_kernel<<<dim3(16, 16, B_BATCH), 256>>>(X);
    softmax_concat_kernel<<<dim3(T_SEQ, B_BATCH), 256>>>(X, sm, out);
    pv_kernel<<<dim3(6, 16, B_BATCH), 256>>>(X, out);
}